// round 16
// baseline (speedup 1.0000x reference)
#include <cuda_runtime.h>
#include <cuda_fp16.h>
#include <cuda_bf16.h>
#include <cstdint>
#include <math_constants.h>

#define N_NODES 8192
#define D_FEAT  512
#define KNN     30
#define KP1     31
#define NTGT    33      // approx-rank margin target (12-sigma capture margin)
#define NCAP    64
#define HALF_E  (N_NODES * KP1)
#define KB      64
#define NB      (D_FEAT / KB)
#define SPITCH  68      // column pitch in floats: 16B-aligned, stride%32==4 -> LDS.128 conflict-free

// ---------------- static device scratch ----------------
__device__ float  g_xn[(size_t)N_NODES * D_FEAT];                     // 16 MB
__device__ __align__(16) __half g_xh[(size_t)N_NODES * D_FEAT];       // 8 MB
__device__ __align__(16) __half g_simh[(size_t)N_NODES * N_NODES];    // 128 MB
__device__ int    g_cand[(size_t)N_NODES * NCAP];
__device__ int    g_ccnt[N_NODES];
__device__ float  g_vals[(size_t)N_NODES * KP1];
__device__ int    g_inds[(size_t)N_NODES * KP1];
__device__ float  g_norm[N_NODES];

// ---------------- helpers ----------------
__device__ __forceinline__ uint32_t smem_u32(const void* p) {
    uint32_t a;
    asm("{ .reg .u64 t; cvta.to.shared.u64 t, %1; cvt.u32.u64 %0, t; }"
        : "=r"(a) : "l"(p));
    return a;
}
__device__ __forceinline__ void cp_async16(uint32_t dst, const void* src) {
    asm volatile("cp.async.ca.shared.global [%0], [%1], 16;"
                 :: "r"(dst), "l"(src) : "memory");
}

// ---------------- row normalize + fp16 copy ----------------
__global__ void normalize_kernel(const float* __restrict__ x) {
    int row = blockIdx.x;
    int t   = threadIdx.x;
    if (t == 0) g_norm[row] = 0.f;
    const float4* xr = (const float4*)(x + (size_t)row * D_FEAT);
    float4 v = xr[t];
    float ss = v.x * v.x + v.y * v.y + v.z * v.z + v.w * v.w;
    #pragma unroll
    for (int o = 16; o; o >>= 1) ss += __shfl_down_sync(0xffffffffu, ss, o);
    __shared__ float ws[4];
    if ((t & 31) == 0) ws[t >> 5] = ss;
    __syncthreads();
    float nrm = __fsqrt_rn(ws[0] + ws[1] + ws[2] + ws[3]);
    float4 o4;
    o4.x = __fdiv_rn(v.x, nrm); o4.y = __fdiv_rn(v.y, nrm);
    o4.z = __fdiv_rn(v.z, nrm); o4.w = __fdiv_rn(v.w, nrm);
    ((float4*)(g_xn + (size_t)row * D_FEAT))[t] = o4;
    __half2* hp = (__half2*)(g_xh + (size_t)row * D_FEAT);
    hp[t * 2]     = __floats2half2_rn(o4.x, o4.y);
    hp[t * 2 + 1] = __floats2half2_rn(o4.z, o4.w);
}

// ------------- approx symmetric GEMM: fp16 HMMA, fp32 accum, fp16 out -------
__device__ __forceinline__ void mma16816(float* d, const uint32_t* a, const uint32_t* b) {
    asm volatile(
        "mma.sync.aligned.m16n8k16.row.col.f32.f16.f16.f32 "
        "{%0,%1,%2,%3}, {%4,%5,%6,%7}, {%8,%9}, {%0,%1,%2,%3};"
        : "+f"(d[0]), "+f"(d[1]), "+f"(d[2]), "+f"(d[3])
        : "r"(a[0]), "r"(a[1]), "r"(a[2]), "r"(a[3]), "r"(b[0]), "r"(b[1]));
}

#define HPITCH 20
#define TPITCH 136
#define BUF_BYTES (128 * HPITCH * 4)

__global__ __launch_bounds__(256) void hgemm_sym_kernel() {
    int bx = blockIdx.x, by = blockIdx.y;
    if (bx > by) return;

    __shared__ __align__(16) char smem_raw[4 * BUF_BYTES];
    __half (*tile)[TPITCH] = (__half(*)[TPITCH])smem_raw;
    uint32_t sbase = smem_u32(smem_raw);

    int t = threadIdx.x, lane = t & 31, w = t >> 5;
    int warpM = (w & 1) * 64, warpN = (w >> 1) * 32;
    int qr = lane >> 2, qc = lane & 3;

    const __half* Ag = g_xh + (size_t)(by * 128) * D_FEAT;
    const __half* Bg = g_xh + (size_t)(bx * 128) * D_FEAT;

    int nd0 = t >> 2,         ko0 = (t & 3) * 8;
    int nd1 = (t + 256) >> 2, ko1 = ((t + 256) & 3) * 8;
    uint32_t so0 = (uint32_t)(nd0 * HPITCH + (ko0 >> 1)) * 4;
    uint32_t so1 = (uint32_t)(nd1 * HPITCH + (ko1 >> 1)) * 4;

    float d[4][4][4];
    #pragma unroll
    for (int i = 0; i < 4; i++)
        #pragma unroll
        for (int j = 0; j < 4; j++)
            #pragma unroll
            for (int c = 0; c < 4; c++) d[i][j][c] = 0.f;

    auto issue = [&](int ch, int buf) {
        uint32_t a_s = sbase + (uint32_t)(buf * 2) * BUF_BYTES;
        uint32_t b_s = a_s + BUF_BYTES;
        int k0 = ch * 32;
        cp_async16(a_s + so0, Ag + (size_t)nd0 * D_FEAT + k0 + ko0);
        cp_async16(a_s + so1, Ag + (size_t)nd1 * D_FEAT + k0 + ko1);
        cp_async16(b_s + so0, Bg + (size_t)nd0 * D_FEAT + k0 + ko0);
        cp_async16(b_s + so1, Bg + (size_t)nd1 * D_FEAT + k0 + ko1);
        asm volatile("cp.async.commit_group;" ::: "memory");
    };

    issue(0, 0);
    for (int ch = 0; ch < 16; ch++) {
        int buf = ch & 1;
        if (ch < 15) issue(ch + 1, buf ^ 1);
        if (ch < 15) asm volatile("cp.async.wait_group 1;" ::: "memory");
        else         asm volatile("cp.async.wait_group 0;" ::: "memory");
        __syncthreads();

        const uint32_t (*As2)[HPITCH] =
            (const uint32_t(*)[HPITCH])(smem_raw + (buf * 2) * BUF_BYTES);
        const uint32_t (*Bs2)[HPITCH] =
            (const uint32_t(*)[HPITCH])(smem_raw + (buf * 2 + 1) * BUF_BYTES);

        #pragma unroll
        for (int kb = 0; kb < 2; kb++) {
            int khb = kb * 8;
            uint32_t a[4][4], b[4][2];
            #pragma unroll
            for (int mt = 0; mt < 4; mt++) {
                int m = warpM + mt * 16 + qr;
                a[mt][0] = As2[m][khb + qc];
                a[mt][1] = As2[m + 8][khb + qc];
                a[mt][2] = As2[m][khb + 4 + qc];
                a[mt][3] = As2[m + 8][khb + 4 + qc];
            }
            #pragma unroll
            for (int nt = 0; nt < 4; nt++) {
                int n = warpN + nt * 8 + qr;
                b[nt][0] = Bs2[n][khb + qc];
                b[nt][1] = Bs2[n][khb + 4 + qc];
            }
            #pragma unroll
            for (int mt = 0; mt < 4; mt++)
                #pragma unroll
                for (int nt = 0; nt < 4; nt++)
                    mma16816(d[mt][nt], a[mt], b[nt]);
        }
        __syncthreads();
    }

    #pragma unroll
    for (int mt = 0; mt < 4; mt++) {
        #pragma unroll
        for (int nt = 0; nt < 4; nt++) {
            int ml = warpM + mt * 16 + qr;
            int nl = warpN + nt * 8 + qc * 2;
            *(__half2*)&tile[ml][nl]     = __floats2half2_rn(d[mt][nt][0], d[mt][nt][1]);
            *(__half2*)&tile[ml + 8][nl] = __floats2half2_rn(d[mt][nt][2], d[mt][nt][3]);
        }
    }
    __syncthreads();

    if (t < 128) {
        uint4* dst = (uint4*)&g_simh[(size_t)(by * 128 + t) * N_NODES + bx * 128];
        const uint4* src = (const uint4*)&tile[t][0];
        #pragma unroll
        for (int u = 0; u < 16; u++) dst[u] = src[u];
    } else if (bx != by) {
        int n = t - 128;
        uint4* dst = (uint4*)&g_simh[(size_t)(bx * 128 + n) * N_NODES + by * 128];
        #pragma unroll
        for (int u = 0; u < 16; u++) {
            __half tmp[8];
            #pragma unroll
            for (int q = 0; q < 8; q++) tmp[q] = tile[u * 8 + q][n];
            dst[u] = *(uint4*)tmp;
        }
    }
}

// ------------- histogram select: per-row approx top-NTGT candidates --------
__device__ __forceinline__ int half_key(uint32_t h) {
    return (h & 0x8000u) ? (int)(~h & 0xFFFFu) : (int)(h | 0x8000u);
}

__global__ __launch_bounds__(256) void select_kernel() {
    __shared__ uint32_t hist[1024];
    __shared__ uint32_t subh[64];
    __shared__ int s_B, s_base, s_cutKey;
    __shared__ int s_ctr;

    int row = blockIdx.x;
    int t   = threadIdx.x;

    for (int i = t; i < 1024; i += 256) hist[i] = 0;
    if (t < 64) subh[t] = 0;
    if (t == 0) s_ctr = 0;
    __syncthreads();

    const uint4* rp = (const uint4*)(g_simh + (size_t)row * N_NODES);
    int key[32];
    #pragma unroll
    for (int m = 0; m < 4; m++) {
        uint4 v = rp[t + 256 * m];
        uint32_t u[4] = {v.x, v.y, v.z, v.w};
        #pragma unroll
        for (int q = 0; q < 4; q++) {
            key[m * 8 + q * 2]     = half_key(u[q] & 0xFFFFu);
            key[m * 8 + q * 2 + 1] = half_key(u[q] >> 16);
        }
    }
    #pragma unroll
    for (int j = 0; j < 32; j++) atomicAdd(&hist[key[j] >> 6], 1u);
    __syncthreads();

    if (t < 32) {
        uint32_t s = 0;
        #pragma unroll
        for (int i = 0; i < 32; i++) s += hist[t * 32 + i];
        uint32_t suf = s;
        #pragma unroll
        for (int o = 1; o < 32; o <<= 1) {
            uint32_t v = __shfl_down_sync(0xffffffffu, suf, o);
            if (t + o < 32) suf += v;
        }
        uint32_t above_lane = suf - s;
        if (suf >= NTGT && above_lane < NTGT) {
            uint32_t cum = above_lane;
            for (int i = 31; i >= 0; i--) {
                cum += hist[t * 32 + i];
                if (cum >= NTGT) {
                    s_B    = t * 32 + i;
                    s_base = (int)(cum - hist[t * 32 + i]);
                    break;
                }
            }
        }
    }
    __syncthreads();
    int B = s_B;

    #pragma unroll
    for (int j = 0; j < 32; j++)
        if ((key[j] >> 6) == B) atomicAdd(&subh[key[j] & 63], 1u);
    __syncthreads();
    if (t == 0) {
        int cum = s_base;
        for (int s = 63; s >= 0; s--) {
            cum += (int)subh[s];
            if (cum >= NTGT) { s_cutKey = (B << 6) | s; break; }
        }
    }
    __syncthreads();
    int cutKey = s_cutKey;

    #pragma unroll
    for (int m = 0; m < 4; m++) {
        #pragma unroll
        for (int q = 0; q < 8; q++) {
            int j = m * 8 + q;
            if (key[j] >= cutKey) {
                int slot = atomicAdd(&s_ctr, 1);
                if (slot < NCAP)
                    g_cand[(size_t)row * NCAP + slot] = (t + 256 * m) * 8 + q;
            }
        }
    }
    __syncthreads();
    if (t == 0) g_ccnt[row] = min(s_ctr, NCAP);
}

// ------------- exact rescore v3: column-major scol, vectorized both phases --
// bit-exact ascending-k chain + exact top-31 + fused degree accumulation
__global__ __launch_bounds__(128) void rescore_kernel() {
    __shared__ float srow[D_FEAT];                        // 2 KB
    __shared__ __align__(16) float scol[NCAP][SPITCH];    // 17.4 KB, column-major
    __shared__ float cval[NCAP];
    __shared__ int   ccol[NCAP];
    __shared__ int   scnt;

    int row = blockIdx.x;
    int t   = threadIdx.x;

    ((float4*)srow)[t] = ((const float4*)(g_xn + (size_t)row * D_FEAT))[t];
    if (t == 0) scnt = g_ccnt[row];
    if (t < NCAP) { cval[t] = -CUDART_INF_F; ccol[t] = 0x7fffffff; }
    __syncthreads();
    int cnt = scnt;
    if (t < cnt) ccol[t] = g_cand[(size_t)row * NCAP + t];
    __syncthreads();

    float acc = 0.f;
    for (int b = 0; b < NB; b++) {
        // stage: 16 float4 per candidate per batch, vectorized LDG + STS.128
        int total = cnt * 16;
        for (int idx = t; idx < total; idx += 128) {
            int cand = idx >> 4;
            int j    = idx & 15;
            float4 v = ((const float4*)(g_xn + (size_t)ccol[cand] * D_FEAT + b * KB))[j];
            *(float4*)&scol[cand][j * 4] = v;
        }
        __syncthreads();
        if (t < cnt) {
            #pragma unroll
            for (int q = 0; q < 16; q++) {          // LDS.128, conflict-free (pitch 68)
                float4 v = *(const float4*)&scol[t][q * 4];
                int kk = b * KB + q * 4;
                acc = fmaf(srow[kk + 0], v.x, acc);  // exact ascending-k chain
                acc = fmaf(srow[kk + 1], v.y, acc);
                acc = fmaf(srow[kk + 2], v.z, acc);
                acc = fmaf(srow[kk + 3], v.w, acc);
            }
        }
        __syncthreads();                             // reads done before refill
    }
    if (t < cnt) cval[t] = acc;
    __syncthreads();

    if (t < 32) {
        float rowsum = 0.f;
        for (int p = 0; p < KP1; p++) {
            float v0 = cval[t];      int c0 = ccol[t],      s0 = t;
            float v1 = cval[t + 32]; int c1 = ccol[t + 32], s1 = t + 32;
            float bv; int bc, bs;
            if (v0 > v1 || (v0 == v1 && c0 < c1)) { bv = v0; bc = c0; bs = s0; }
            else                                  { bv = v1; bc = c1; bs = s1; }
            #pragma unroll
            for (int o = 16; o; o >>= 1) {
                float ov = __shfl_down_sync(0xffffffffu, bv, o);
                int   oc = __shfl_down_sync(0xffffffffu, bc, o);
                int   os = __shfl_down_sync(0xffffffffu, bs, o);
                if (ov > bv || (ov == bv && oc < bc)) { bv = ov; bc = oc; bs = os; }
            }
            bv = __shfl_sync(0xffffffffu, bv, 0);
            bc = __shfl_sync(0xffffffffu, bc, 0);
            bs = __shfl_sync(0xffffffffu, bs, 0);
            if (t == 0) {
                g_vals[row * KP1 + p] = bv;
                g_inds[row * KP1 + p] = bc;
                cval[bs] = -CUDART_INF_F;
                rowsum += bv;
                atomicAdd(&g_norm[bc], bv);
            }
            __syncwarp();
        }
        if (t == 0) atomicAdd(&g_norm[row], rowsum);
    }
}

// ---------------- JAX threefry2x32, key = (0, 42) ----------------
__device__ __forceinline__ uint32_t rotl32(uint32_t v, int d) {
    return (v << d) | (v >> (32 - d));
}
__device__ __forceinline__ void threefry2x32_42(uint32_t c0, uint32_t c1,
                                                uint32_t& o0, uint32_t& o1) {
    const uint32_t ks0 = 0u, ks1 = 42u, ks2 = 0u ^ 42u ^ 0x1BD11BDAu;
    uint32_t x0 = c0 + ks0, x1 = c1 + ks1;
    const int ra[4] = {13, 15, 26, 6};
    const int rb[4] = {17, 29, 16, 24};
    #pragma unroll
    for (int i = 0; i < 4; i++) { x0 += x1; x1 = rotl32(x1, ra[i]); x1 ^= x0; }
    x0 += ks1; x1 += ks2 + 1u;
    #pragma unroll
    for (int i = 0; i < 4; i++) { x0 += x1; x1 = rotl32(x1, rb[i]); x1 ^= x0; }
    x0 += ks2; x1 += ks0 + 2u;
    #pragma unroll
    for (int i = 0; i < 4; i++) { x0 += x1; x1 = rotl32(x1, ra[i]); x1 ^= x0; }
    x0 += ks0; x1 += ks1 + 3u;
    #pragma unroll
    for (int i = 0; i < 4; i++) { x0 += x1; x1 = rotl32(x1, rb[i]); x1 ^= x0; }
    x0 += ks1; x1 += ks2 + 4u;
    #pragma unroll
    for (int i = 0; i < 4; i++) { x0 += x1; x1 = rotl32(x1, ra[i]); x1 ^= x0; }
    x0 += ks2; x1 += ks0 + 5u;
    o0 = x0; o1 = x1;
}
__device__ __forceinline__ bool keep_edge(uint32_t i) {
    uint32_t o0, o1;
    threefry2x32_42(0u, i, o0, o1);
    uint32_t b = o0 ^ o1;
    float u = __uint_as_float((b >> 9) | 0x3f800000u) - 1.0f;
    return u < 0.9f;
}

// ---------------- normalize edges + dropout + symmetric scatter-add --------
__global__ void scatter_kernel(float* __restrict__ adj) {
    int i = blockIdx.x * blockDim.x + threadIdx.x;
    if (i >= HALF_E) return;
    int   r = i / KP1;
    int   c = g_inds[i];
    float v = g_vals[i];
    float w = v * __frcp_rn(__fsqrt_rn(g_norm[r]));
    w = w * __frcp_rn(__fsqrt_rn(g_norm[c]));
    if (isnan(w)) w = 0.f;
    w = fmaxf(w, 0.f);

    float w0 = keep_edge((uint32_t)i)            ? (w / 0.9f) : 0.f;
    float w1 = keep_edge((uint32_t)(i + HALF_E)) ? (w / 0.9f) : 0.f;

    atomicAdd(&adj[(size_t)r * N_NODES + c], w0);
    atomicAdd(&adj[(size_t)c * N_NODES + r], w1);
}

// ---------------- launch ----------------
extern "C" void kernel_launch(void* const* d_in, const int* in_sizes, int n_in,
                              void* d_out, int out_size) {
    const float* x  = (const float*)d_in[0];
    float* adj = (float*)d_out;
    (void)in_sizes; (void)n_in; (void)out_size;

    normalize_kernel<<<N_NODES, 128>>>(x);

    dim3 ggrid(N_NODES / 128, N_NODES / 128);
    hgemm_sym_kernel<<<ggrid, 256>>>();

    select_kernel<<<N_NODES, 256>>>();
    rescore_kernel<<<N_NODES, 128>>>();

    // zero 256MB adjacency via driver memset (graph-capturable, no alloc)
    cudaMemsetAsync(adj, 0, (size_t)N_NODES * N_NODES * sizeof(float));
    scatter_kernel<<<(HALF_E + 255) / 256, 256>>>(adj);
}

// round 17
// speedup vs baseline: 1.0479x; 1.0479x over previous
#include <cuda_runtime.h>
#include <cuda_fp16.h>
#include <cuda_bf16.h>
#include <cstdint>
#include <math_constants.h>

#define N_NODES 8192
#define D_FEAT  512
#define KNN     30
#define KP1     31
#define NTGT    33      // approx-rank margin target (12-sigma capture margin)
#define NCAP    64
#define HALF_E  (N_NODES * KP1)
#define KB      64
#define NB      (D_FEAT / KB)

// ---------------- static device scratch ----------------
__device__ float  g_xn[(size_t)N_NODES * D_FEAT];                     // 16 MB
__device__ __align__(16) __half g_xh[(size_t)N_NODES * D_FEAT];       // 8 MB
__device__ __align__(16) __half g_simh[(size_t)N_NODES * N_NODES];    // 128 MB
__device__ int    g_cand[(size_t)N_NODES * NCAP];
__device__ int    g_ccnt[N_NODES];
__device__ float  g_vals[(size_t)N_NODES * KP1];
__device__ int    g_inds[(size_t)N_NODES * KP1];
__device__ float  g_norm[N_NODES];

// ---------------- helpers ----------------
__device__ __forceinline__ uint32_t smem_u32(const void* p) {
    uint32_t a;
    asm("{ .reg .u64 t; cvta.to.shared.u64 t, %1; cvt.u32.u64 %0, t; }"
        : "=r"(a) : "l"(p));
    return a;
}
__device__ __forceinline__ void cp_async16(uint32_t dst, const void* src) {
    asm volatile("cp.async.ca.shared.global [%0], [%1], 16;"
                 :: "r"(dst), "l"(src) : "memory");
}
__device__ __forceinline__ void ldsm_x4(uint32_t* r, uint32_t addr) {
    asm volatile("ldmatrix.sync.aligned.m8n8.x4.shared.b16 {%0,%1,%2,%3}, [%4];"
                 : "=r"(r[0]), "=r"(r[1]), "=r"(r[2]), "=r"(r[3]) : "r"(addr));
}
__device__ __forceinline__ void ldsm_x2(uint32_t* r, uint32_t addr) {
    asm volatile("ldmatrix.sync.aligned.m8n8.x2.shared.b16 {%0,%1}, [%2];"
                 : "=r"(r[0]), "=r"(r[1]) : "r"(addr));
}

// ---------------- row normalize + fp16 copy ----------------
__global__ void normalize_kernel(const float* __restrict__ x) {
    int row = blockIdx.x;
    int t   = threadIdx.x;
    if (t == 0) g_norm[row] = 0.f;
    const float4* xr = (const float4*)(x + (size_t)row * D_FEAT);
    float4 v = xr[t];
    float ss = v.x * v.x + v.y * v.y + v.z * v.z + v.w * v.w;
    #pragma unroll
    for (int o = 16; o; o >>= 1) ss += __shfl_down_sync(0xffffffffu, ss, o);
    __shared__ float ws[4];
    if ((t & 31) == 0) ws[t >> 5] = ss;
    __syncthreads();
    float nrm = __fsqrt_rn(ws[0] + ws[1] + ws[2] + ws[3]);
    float4 o4;
    o4.x = __fdiv_rn(v.x, nrm); o4.y = __fdiv_rn(v.y, nrm);
    o4.z = __fdiv_rn(v.z, nrm); o4.w = __fdiv_rn(v.w, nrm);
    ((float4*)(g_xn + (size_t)row * D_FEAT))[t] = o4;
    __half2* hp = (__half2*)(g_xh + (size_t)row * D_FEAT);
    hp[t * 2]     = __floats2half2_rn(o4.x, o4.y);
    hp[t * 2 + 1] = __floats2half2_rn(o4.z, o4.w);
}

// ------------- approx symmetric GEMM: fp16 HMMA, fp32 accum, fp16 out -------
// cp.async double-buffered pipeline + ldmatrix fragment loads.
__device__ __forceinline__ void mma16816(float* d, const uint32_t* a, const uint32_t* b) {
    asm volatile(
        "mma.sync.aligned.m16n8k16.row.col.f32.f16.f16.f32 "
        "{%0,%1,%2,%3}, {%4,%5,%6,%7}, {%8,%9}, {%0,%1,%2,%3};"
        : "+f"(d[0]), "+f"(d[1]), "+f"(d[2]), "+f"(d[3])
        : "r"(a[0]), "r"(a[1]), "r"(a[2]), "r"(a[3]), "r"(b[0]), "r"(b[1]));
}

#define HPITCH 20
#define TPITCH 136
#define BUF_BYTES (128 * HPITCH * 4)

__global__ __launch_bounds__(256) void hgemm_sym_kernel() {
    int bx = blockIdx.x, by = blockIdx.y;
    if (bx > by) return;

    __shared__ __align__(16) char smem_raw[4 * BUF_BYTES];
    __half (*tile)[TPITCH] = (__half(*)[TPITCH])smem_raw;
    uint32_t sbase = smem_u32(smem_raw);

    int t = threadIdx.x, lane = t & 31, w = t >> 5;
    int warpM = (w & 1) * 64, warpN = (w >> 1) * 32;
    int qr = lane >> 2, qc = lane & 3;

    const __half* Ag = g_xh + (size_t)(by * 128) * D_FEAT;
    const __half* Bg = g_xh + (size_t)(bx * 128) * D_FEAT;

    int nd0 = t >> 2,         ko0 = (t & 3) * 8;
    int nd1 = (t + 256) >> 2, ko1 = ((t + 256) & 3) * 8;
    uint32_t so0 = (uint32_t)(nd0 * HPITCH + (ko0 >> 1)) * 4;
    uint32_t so1 = (uint32_t)(nd1 * HPITCH + (ko1 >> 1)) * 4;

    // ldmatrix per-lane address components (words)
    int a_row  = warpM + (lane & 15);          // + mt*16
    int a_coff = (lane >> 4) * 4;              // k-half-group select
    int b_row  = warpN + (lane & 7);           // + nt*8
    int b_coff = ((lane >> 3) & 1) * 4;

    float d[4][4][4];
    #pragma unroll
    for (int i = 0; i < 4; i++)
        #pragma unroll
        for (int j = 0; j < 4; j++)
            #pragma unroll
            for (int c = 0; c < 4; c++) d[i][j][c] = 0.f;

    auto issue = [&](int ch, int buf) {
        uint32_t a_s = sbase + (uint32_t)(buf * 2) * BUF_BYTES;
        uint32_t b_s = a_s + BUF_BYTES;
        int k0 = ch * 32;
        cp_async16(a_s + so0, Ag + (size_t)nd0 * D_FEAT + k0 + ko0);
        cp_async16(a_s + so1, Ag + (size_t)nd1 * D_FEAT + k0 + ko1);
        cp_async16(b_s + so0, Bg + (size_t)nd0 * D_FEAT + k0 + ko0);
        cp_async16(b_s + so1, Bg + (size_t)nd1 * D_FEAT + k0 + ko1);
        asm volatile("cp.async.commit_group;" ::: "memory");
    };

    issue(0, 0);
    for (int ch = 0; ch < 16; ch++) {
        int buf = ch & 1;
        if (ch < 15) issue(ch + 1, buf ^ 1);
        if (ch < 15) asm volatile("cp.async.wait_group 1;" ::: "memory");
        else         asm volatile("cp.async.wait_group 0;" ::: "memory");
        __syncthreads();

        uint32_t a_s = sbase + (uint32_t)(buf * 2) * BUF_BYTES;
        uint32_t b_s = a_s + BUF_BYTES;

        #pragma unroll
        for (int kb = 0; kb < 2; kb++) {
            int khb = kb * 8;
            uint32_t a[4][4], b[4][2];
            #pragma unroll
            for (int mt = 0; mt < 4; mt++)
                ldsm_x4(a[mt], a_s + (uint32_t)((a_row + mt * 16) * HPITCH
                                                + khb + a_coff) * 4u);
            #pragma unroll
            for (int nt = 0; nt < 4; nt++)
                ldsm_x2(b[nt], b_s + (uint32_t)((b_row + nt * 8) * HPITCH
                                                + khb + b_coff) * 4u);
            #pragma unroll
            for (int mt = 0; mt < 4; mt++)
                #pragma unroll
                for (int nt = 0; nt < 4; nt++)
                    mma16816(d[mt][nt], a[mt], b[nt]);
        }
        __syncthreads();
    }

    // ---- staged epilogue: fp16 tile in smem, coalesced row writes ----
    #pragma unroll
    for (int mt = 0; mt < 4; mt++) {
        #pragma unroll
        for (int nt = 0; nt < 4; nt++) {
            int ml = warpM + mt * 16 + qr;
            int nl = warpN + nt * 8 + qc * 2;
            *(__half2*)&tile[ml][nl]     = __floats2half2_rn(d[mt][nt][0], d[mt][nt][1]);
            *(__half2*)&tile[ml + 8][nl] = __floats2half2_rn(d[mt][nt][2], d[mt][nt][3]);
        }
    }
    __syncthreads();

    if (t < 128) {
        uint4* dst = (uint4*)&g_simh[(size_t)(by * 128 + t) * N_NODES + bx * 128];
        const uint4* src = (const uint4*)&tile[t][0];
        #pragma unroll
        for (int u = 0; u < 16; u++) dst[u] = src[u];
    } else if (bx != by) {
        int n = t - 128;
        uint4* dst = (uint4*)&g_simh[(size_t)(bx * 128 + n) * N_NODES + by * 128];
        #pragma unroll
        for (int u = 0; u < 16; u++) {
            __half tmp[8];
            #pragma unroll
            for (int q = 0; q < 8; q++) tmp[q] = tile[u * 8 + q][n];
            dst[u] = *(uint4*)tmp;
        }
    }
}

// ------------- histogram select: per-row approx top-NTGT candidates --------
__device__ __forceinline__ int half_key(uint32_t h) {
    return (h & 0x8000u) ? (int)(~h & 0xFFFFu) : (int)(h | 0x8000u);
}

__global__ __launch_bounds__(256) void select_kernel() {
    __shared__ uint32_t hist[1024];
    __shared__ uint32_t subh[64];
    __shared__ int s_B, s_base, s_cutKey;
    __shared__ int s_ctr;

    int row = blockIdx.x;
    int t   = threadIdx.x;

    for (int i = t; i < 1024; i += 256) hist[i] = 0;
    if (t < 64) subh[t] = 0;
    if (t == 0) s_ctr = 0;
    __syncthreads();

    const uint4* rp = (const uint4*)(g_simh + (size_t)row * N_NODES);
    int key[32];
    #pragma unroll
    for (int m = 0; m < 4; m++) {
        uint4 v = rp[t + 256 * m];
        uint32_t u[4] = {v.x, v.y, v.z, v.w};
        #pragma unroll
        for (int q = 0; q < 4; q++) {
            key[m * 8 + q * 2]     = half_key(u[q] & 0xFFFFu);
            key[m * 8 + q * 2 + 1] = half_key(u[q] >> 16);
        }
    }
    #pragma unroll
    for (int j = 0; j < 32; j++) atomicAdd(&hist[key[j] >> 6], 1u);
    __syncthreads();

    if (t < 32) {
        uint32_t s = 0;
        #pragma unroll
        for (int i = 0; i < 32; i++) s += hist[t * 32 + i];
        uint32_t suf = s;
        #pragma unroll
        for (int o = 1; o < 32; o <<= 1) {
            uint32_t v = __shfl_down_sync(0xffffffffu, suf, o);
            if (t + o < 32) suf += v;
        }
        uint32_t above_lane = suf - s;
        if (suf >= NTGT && above_lane < NTGT) {
            uint32_t cum = above_lane;
            for (int i = 31; i >= 0; i--) {
                cum += hist[t * 32 + i];
                if (cum >= NTGT) {
                    s_B    = t * 32 + i;
                    s_base = (int)(cum - hist[t * 32 + i]);
                    break;
                }
            }
        }
    }
    __syncthreads();
    int B = s_B;

    #pragma unroll
    for (int j = 0; j < 32; j++)
        if ((key[j] >> 6) == B) atomicAdd(&subh[key[j] & 63], 1u);
    __syncthreads();
    if (t == 0) {
        int cum = s_base;
        for (int s = 63; s >= 0; s--) {
            cum += (int)subh[s];
            if (cum >= NTGT) { s_cutKey = (B << 6) | s; break; }
        }
    }
    __syncthreads();
    int cutKey = s_cutKey;

    #pragma unroll
    for (int m = 0; m < 4; m++) {
        #pragma unroll
        for (int q = 0; q < 8; q++) {
            int j = m * 8 + q;
            if (key[j] >= cutKey) {
                int slot = atomicAdd(&s_ctr, 1);
                if (slot < NCAP)
                    g_cand[(size_t)row * NCAP + slot] = (t + 256 * m) * 8 + q;
            }
        }
    }
    __syncthreads();
    if (t == 0) g_ccnt[row] = min(s_ctr, NCAP);
}

// ------------- exact rescore (frozen round-13 frontier version) -------------
__global__ __launch_bounds__(128) void rescore_kernel() {
    __shared__ float srow[D_FEAT];
    __shared__ float scolT[KB][NCAP + 1];
    __shared__ float cval[NCAP];
    __shared__ int   ccol[NCAP];
    __shared__ int   scnt;

    int row = blockIdx.x;
    int t   = threadIdx.x;

    ((float4*)srow)[t] = ((const float4*)(g_xn + (size_t)row * D_FEAT))[t];
    if (t == 0) scnt = g_ccnt[row];
    if (t < NCAP) { cval[t] = -CUDART_INF_F; ccol[t] = 0x7fffffff; }
    __syncthreads();
    int cnt = scnt;
    if (t < cnt) ccol[t] = g_cand[(size_t)row * NCAP + t];
    __syncthreads();

    float acc = 0.f;
    int ci = t >> 3;
    int j  = t & 7;
    for (int b = 0; b < NB; b++) {
        __syncthreads();
        for (int cg = ci; cg < cnt; cg += 16) {
            const float4* cp = (const float4*)(g_xn + (size_t)ccol[cg] * D_FEAT + b * KB);
            float4 v0 = cp[j];
            float4 v1 = cp[j + 8];
            int k0 = j * 4, k1 = (j + 8) * 4;
            scolT[k0 + 0][cg] = v0.x; scolT[k0 + 1][cg] = v0.y;
            scolT[k0 + 2][cg] = v0.z; scolT[k0 + 3][cg] = v0.w;
            scolT[k1 + 0][cg] = v1.x; scolT[k1 + 1][cg] = v1.y;
            scolT[k1 + 2][cg] = v1.z; scolT[k1 + 3][cg] = v1.w;
        }
        __syncthreads();
        if (t < cnt) {
            #pragma unroll 16
            for (int kk = 0; kk < KB; kk++)
                acc = fmaf(srow[b * KB + kk], scolT[kk][t], acc);  // exact chain
        }
    }
    if (t < cnt) cval[t] = acc;
    __syncthreads();

    if (t < 32) {
        float rowsum = 0.f;
        for (int p = 0; p < KP1; p++) {
            float v0 = cval[t];      int c0 = ccol[t],      s0 = t;
            float v1 = cval[t + 32]; int c1 = ccol[t + 32], s1 = t + 32;
            float bv; int bc, bs;
            if (v0 > v1 || (v0 == v1 && c0 < c1)) { bv = v0; bc = c0; bs = s0; }
            else                                  { bv = v1; bc = c1; bs = s1; }
            #pragma unroll
            for (int o = 16; o; o >>= 1) {
                float ov = __shfl_down_sync(0xffffffffu, bv, o);
                int   oc = __shfl_down_sync(0xffffffffu, bc, o);
                int   os = __shfl_down_sync(0xffffffffu, bs, o);
                if (ov > bv || (ov == bv && oc < bc)) { bv = ov; bc = oc; bs = os; }
            }
            bv = __shfl_sync(0xffffffffu, bv, 0);
            bc = __shfl_sync(0xffffffffu, bc, 0);
            bs = __shfl_sync(0xffffffffu, bs, 0);
            if (t == 0) {
                g_vals[row * KP1 + p] = bv;
                g_inds[row * KP1 + p] = bc;
                cval[bs] = -CUDART_INF_F;
                rowsum += bv;
                atomicAdd(&g_norm[bc], bv);
            }
            __syncwarp();
        }
        if (t == 0) atomicAdd(&g_norm[row], rowsum);
    }
}

// ---------------- JAX threefry2x32, key = (0, 42) ----------------
__device__ __forceinline__ uint32_t rotl32(uint32_t v, int d) {
    return (v << d) | (v >> (32 - d));
}
__device__ __forceinline__ void threefry2x32_42(uint32_t c0, uint32_t c1,
                                                uint32_t& o0, uint32_t& o1) {
    const uint32_t ks0 = 0u, ks1 = 42u, ks2 = 0u ^ 42u ^ 0x1BD11BDAu;
    uint32_t x0 = c0 + ks0, x1 = c1 + ks1;
    const int ra[4] = {13, 15, 26, 6};
    const int rb[4] = {17, 29, 16, 24};
    #pragma unroll
    for (int i = 0; i < 4; i++) { x0 += x1; x1 = rotl32(x1, ra[i]); x1 ^= x0; }
    x0 += ks1; x1 += ks2 + 1u;
    #pragma unroll
    for (int i = 0; i < 4; i++) { x0 += x1; x1 = rotl32(x1, rb[i]); x1 ^= x0; }
    x0 += ks2; x1 += ks0 + 2u;
    #pragma unroll
    for (int i = 0; i < 4; i++) { x0 += x1; x1 = rotl32(x1, ra[i]); x1 ^= x0; }
    x0 += ks0; x1 += ks1 + 3u;
    #pragma unroll
    for (int i = 0; i < 4; i++) { x0 += x1; x1 = rotl32(x1, rb[i]); x1 ^= x0; }
    x0 += ks1; x1 += ks2 + 4u;
    #pragma unroll
    for (int i = 0; i < 4; i++) { x0 += x1; x1 = rotl32(x1, ra[i]); x1 ^= x0; }
    x0 += ks2; x1 += ks0 + 5u;
    o0 = x0; o1 = x1;
}
__device__ __forceinline__ bool keep_edge(uint32_t i) {
    uint32_t o0, o1;
    threefry2x32_42(0u, i, o0, o1);
    uint32_t b = o0 ^ o1;
    float u = __uint_as_float((b >> 9) | 0x3f800000u) - 1.0f;
    return u < 0.9f;
}

// ---------------- normalize edges + dropout + symmetric scatter-add --------
__global__ void scatter_kernel(float* __restrict__ adj) {
    int i = blockIdx.x * blockDim.x + threadIdx.x;
    if (i >= HALF_E) return;
    int   r = i / KP1;
    int   c = g_inds[i];
    float v = g_vals[i];
    float w = v * __frcp_rn(__fsqrt_rn(g_norm[r]));
    w = w * __frcp_rn(__fsqrt_rn(g_norm[c]));
    if (isnan(w)) w = 0.f;
    w = fmaxf(w, 0.f);

    float w0 = keep_edge((uint32_t)i)            ? (w / 0.9f) : 0.f;
    float w1 = keep_edge((uint32_t)(i + HALF_E)) ? (w / 0.9f) : 0.f;

    atomicAdd(&adj[(size_t)r * N_NODES + c], w0);
    atomicAdd(&adj[(size_t)c * N_NODES + r], w1);
}

// ---------------- launch ----------------
extern "C" void kernel_launch(void* const* d_in, const int* in_sizes, int n_in,
                              void* d_out, int out_size) {
    const float* x  = (const float*)d_in[0];
    float* adj = (float*)d_out;
    (void)in_sizes; (void)n_in; (void)out_size;

    normalize_kernel<<<N_NODES, 128>>>(x);

    dim3 ggrid(N_NODES / 128, N_NODES / 128);
    hgemm_sym_kernel<<<ggrid, 256>>>();

    select_kernel<<<N_NODES, 256>>>();
    rescore_kernel<<<N_NODES, 128>>>();

    // zero 256MB adjacency via driver memset (graph-capturable, no alloc)
    cudaMemsetAsync(adj, 0, (size_t)N_NODES * N_NODES * sizeof(float));
    scatter_kernel<<<(HALF_E + 255) / 256, 256>>>(adj);
}